// round 2
// baseline (speedup 1.0000x reference)
#include <cuda_runtime.h>
#include <math.h>

#define NH 2
#define NB 2048
#define NM 64
#define ND 16
#define NREL 32

__global__ __launch_bounds__(128, 8)
void ripple_kernel(const int* __restrict__ items,
                   const int* __restrict__ heads,
                   const int* __restrict__ rels,
                   const int* __restrict__ tails,
                   const float* __restrict__ ent,
                   const float* __restrict__ relm,
                   float* __restrict__ out)
{
    const int b    = blockIdx.x;
    const int t    = threadIdx.x;      // 0..127
    const int hop  = t >> 6;           // 0 or 1
    const int m    = t & 63;
    const int lane = t & 31;
    const int wid  = t >> 5;           // 0..3 (warps 0,1 = hop0; 2,3 = hop1)

    __shared__ __align__(16) float item_s[ND];
    __shared__ __align__(16) float q_s[NREL * ND]; // q[r][j] = sum_i R[r][i][j]*item[i]
    __shared__ float red_s[8];

    // ---- load item embedding (16 floats) ----
    const int item_idx = items[b];
    if (t < ND) item_s[t] = ent[(size_t)item_idx * ND + t];
    __syncthreads();

    // ---- precompute q[r][j] for all 32 relations (512 outputs / 128 threads = 4 each) ----
    #pragma unroll
    for (int k = 0; k < 4; k++) {
        int o = t + k * 128;
        int r = o >> 4;
        int j = o & 15;
        const float* rp = relm + r * (ND * ND) + j;   // column j of R_r
        float acc = 0.f;
        #pragma unroll
        for (int i = 0; i < ND; i++) acc += rp[i * ND] * item_s[i];
        q_s[o] = acc;
    }
    __syncthreads();

    // ---- per-slot gather + logit + tail·item ----
    const int gidx = hop * (NB * NM) + b * NM + m;
    const int hidx = heads[gidx];
    const int ridx = rels[gidx];
    const int tidx = tails[gidx];

    const float4* hp = (const float4*)(ent + (size_t)hidx * ND);
    const float4* tp = (const float4*)(ent + (size_t)tidx * ND);
    const float4* qp = (const float4*)(q_s) + ridx * 4;
    const float4* ip = (const float4*)(item_s);

    float logit = 0.f, td = 0.f;
    #pragma unroll
    for (int k = 0; k < 4; k++) {
        float4 hv = hp[k];
        float4 tv = tp[k];
        float4 qv = qp[k];
        float4 iv = ip[k];
        logit += qv.x * hv.x + qv.y * hv.y + qv.z * hv.z + qv.w * hv.w;
        td    += iv.x * tv.x + iv.y * tv.y + iv.z * tv.z + iv.w * tv.w;
    }

    // ---- softmax over the 64 slots of this hop (2 warps) ----
    float mx = logit;
    #pragma unroll
    for (int o = 16; o > 0; o >>= 1)
        mx = fmaxf(mx, __shfl_xor_sync(0xffffffffu, mx, o));
    if (lane == 0) red_s[wid] = mx;
    __syncthreads();
    mx = fmaxf(red_s[hop * 2], red_s[hop * 2 + 1]);

    float e = __expf(logit - mx);
    float sm = e;
    #pragma unroll
    for (int o = 16; o > 0; o >>= 1)
        sm += __shfl_xor_sync(0xffffffffu, sm, o);
    if (lane == 0) red_s[4 + wid] = sm;
    __syncthreads();
    sm = red_s[4 + hop * 2] + red_s[4 + hop * 2 + 1];

    const float pi = e / sm;

    // ---- contribution: pi * (tail · item); block-reduce over 128 threads ----
    float c = pi * td;
    #pragma unroll
    for (int o = 16; o > 0; o >>= 1)
        c += __shfl_xor_sync(0xffffffffu, c, o);
    if (lane == 0) red_s[wid] = c;      // disjoint from red_s[4..7] reads above
    __syncthreads();

    if (t == 0) {
        float total = red_s[0] + red_s[1] + red_s[2] + red_s[3];
        out[b] = 1.f / (1.f + __expf(-total));
    }
}

extern "C" void kernel_launch(void* const* d_in, const int* in_sizes, int n_in,
                              void* d_out, int out_size)
{
    const int*   items = (const int*)d_in[0];
    const int*   heads = (const int*)d_in[1];
    const int*   rels  = (const int*)d_in[2];
    const int*   tails = (const int*)d_in[3];
    const float* ent   = (const float*)d_in[4];
    const float* relm  = (const float*)d_in[5];
    float*       out   = (float*)d_out;

    ripple_kernel<<<NB, 128>>>(items, heads, rels, tails, ent, relm, out);
}